// round 2
// baseline (speedup 1.0000x reference)
#include <cuda_runtime.h>

#define BATCH 8
#define CIN   64
#define COUT  64
#define HH    112
#define WW    112
#define HWSZ  (HH*WW)
#define LTOT  (HH*WW)

// ---------------- packed f32x2 helpers ----------------
__device__ __forceinline__ unsigned long long pk2(float a, float b) {
    unsigned long long r;
    asm("mov.b64 %0, {%1, %2};" : "=l"(r) : "f"(a), "f"(b));
    return r;
}
__device__ __forceinline__ void upk2(unsigned long long v, float& a, float& b) {
    asm("mov.b64 {%0, %1}, %2;" : "=f"(a), "=f"(b) : "l"(v));
}
__device__ __forceinline__ void ffma2(unsigned long long& d,
                                      unsigned long long a, unsigned long long b) {
    asm("fma.rn.f32x2 %0, %1, %2, %0;" : "+l"(d) : "l"(a), "l"(b));
}

// ================= K1: pure (unmasked) 3x3 conv =================
#define TH 8
#define TW 16
#define IN_H 10
#define IN_W 18
#define IN_STRIDE 20       // 16B-aligned rows for float4 LDS
#define NT1 256

__global__ __launch_bounds__(NT1, 2)
void conv_kernel(const float* __restrict__ x,
                 const float* __restrict__ w,
                 float*       __restrict__ out)
{
    __shared__ float  s_in[2][IN_H * IN_STRIDE];
    __shared__ __align__(16) float2 s_w[2][9 * COUT];   // duplicated {w,w}, layout [t][o]

    const int tid   = threadIdx.x;
    const int o_grp = tid >> 5;            // warp -> 8 output channels
    const int lane  = tid & 31;
    const int row   = lane >> 2;           // 0..7
    const int x0    = (lane & 3) << 2;     // 0,4,8,12

    const int gx0 = blockIdx.x * TW;
    const int gy0 = blockIdx.y * TH;
    const int b   = blockIdx.z;
    const int y   = gy0 + row;

    const float* xb = x + (size_t)b * CIN * HWSZ;

    // ---- loader precompute (hoisted out of channel loop) ----
    // input tile: one element per thread (tid < 180)
    bool in_act = tid < IN_H * IN_W;
    int  r_in = 0, c_in = 0;
    bool in_pred = false;
    const float* gin = xb;
    int sts_idx = 0;
    if (in_act) {
        r_in = tid / IN_W;
        c_in = tid - r_in * IN_W;
        int gy = gy0 - 1 + r_in;
        int gx = gx0 - 1 + c_in;
        in_pred = (gy >= 0 && gy < HH && gx >= 0 && gx < WW);
        gin = xb + (in_pred ? (gy * WW + gx) : 0);
        sts_idx = r_in * IN_STRIDE + c_in;
    }
    // weight entries: up to 3 per thread; smem layout [t][o]
    int widx[3];
    const float* wg[3];
    bool wact[3];
    #pragma unroll
    for (int k = 0; k < 3; k++) {
        int e = tid + k * 256;
        wact[k] = (e < 576);
        int o = 0, t = 0;
        if (wact[k]) { o = e / 9; t = e - 9 * o; }
        widx[k] = t * 64 + o;
        wg[k]   = w + o * (CIN * 9) + t;   // + c*9 per channel
    }

    // ---- prefetch channel 0 into registers ----
    float vin = (in_act && in_pred) ? __ldg(gin) : 0.0f;
    float vwr[3];
    #pragma unroll
    for (int k = 0; k < 3; k++) vwr[k] = wact[k] ? __ldg(wg[k]) : 0.0f;

    unsigned long long acc[8][2];
    #pragma unroll
    for (int o = 0; o < 8; o++) { acc[o][0] = 0ull; acc[o][1] = 0ull; }

    int buf = 0;
    for (int c = 0; c < CIN; c++) {
        // stage prefetched channel into smem
        if (in_act) s_in[buf][sts_idx] = in_pred ? vin : 0.0f;
        #pragma unroll
        for (int k = 0; k < 3; k++)
            if (wact[k]) s_w[buf][widx[k]] = make_float2(vwr[k], vwr[k]);
        __syncthreads();

        // prefetch next channel (LDG latency hides under compute)
        if (c + 1 < CIN) {
            if (in_act && in_pred) vin = __ldg(gin + (c + 1) * HWSZ);
            #pragma unroll
            for (int k = 0; k < 3; k++)
                if (wact[k]) vwr[k] = __ldg(wg[k] + (c + 1) * 9);
        }

        // register-cache the 3x8 input window
        float iv[3][8];
        const float* sb = s_in[buf];
        #pragma unroll
        for (int kh = 0; kh < 3; kh++) {
            float4 a = *reinterpret_cast<const float4*>(&sb[(row + kh) * IN_STRIDE + x0]);
            float4 bq = *reinterpret_cast<const float4*>(&sb[(row + kh) * IN_STRIDE + x0 + 4]);
            iv[kh][0] = a.x;  iv[kh][1] = a.y;  iv[kh][2] = a.z;  iv[kh][3] = a.w;
            iv[kh][4] = bq.x; iv[kh][5] = bq.y; iv[kh][6] = bq.z; iv[kh][7] = bq.w;
        }

        const float2* ws = &s_w[buf][o_grp * 8];
        #pragma unroll
        for (int kh = 0; kh < 3; kh++) {
            #pragma unroll
            for (int kw = 0; kw < 3; kw++) {
                const int t = kh * 3 + kw;
                unsigned long long v0 = pk2(iv[kh][kw + 0], iv[kh][kw + 1]);
                unsigned long long v1 = pk2(iv[kh][kw + 2], iv[kh][kw + 3]);
                #pragma unroll
                for (int o = 0; o < 8; o++) {
                    unsigned long long wv =
                        *reinterpret_cast<const unsigned long long*>(&ws[t * 64 + o]);
                    ffma2(acc[o][0], v0, wv);
                    ffma2(acc[o][1], v1, wv);
                }
            }
        }
        __syncthreads();
        buf ^= 1;
    }

    // store: 8 o x 4 contiguous x per thread (float4, 16B aligned)
    const int o_base = o_grp * 8;
    #pragma unroll
    for (int o = 0; o < 8; o++) {
        float f0, f1, f2, f3;
        upk2(acc[o][0], f0, f1);
        upk2(acc[o][1], f2, f3);
        float* dst = out + ((((size_t)b * COUT + o_base + o) * HH + y) * WW + gx0 + x0);
        *reinterpret_cast<float4*>(dst) = make_float4(f0, f1, f2, f3);
    }
}

// ================= K2: subtract masked-tap correction =================
// out[b,o,l] -= sum_c x[b,c,masked_pos(l)] * w[o,c,m[l]]
#define K2_TSTRIDE 66              // padded t-stride -> conflict-free tap-indexed LDS
#define K2_CSTRIDE (9 * K2_TSTRIDE)

__global__ __launch_bounds__(256, 2)
void corr_kernel(const float* __restrict__ x,
                 const float* __restrict__ w,
                 const int*   __restrict__ mask,
                 float*       __restrict__ out)
{
    __shared__ int   s_off[256];
    __shared__ float s_x[8 * 256];
    __shared__ __align__(16) float s_w[8 * K2_CSTRIDE];

    const int tid = threadIdx.x;
    const int b   = blockIdx.y;
    const int l   = blockIdx.x * 256 + tid;

    const int t  = mask[l];
    const int yy = l / WW;
    const int xx = l - yy * WW;
    const int kh = t / 3;
    const int kw = t - kh * 3;
    const int ym = yy + kh - 1;
    const int xm = xx + kw - 1;
    const int off = (ym >= 0 && ym < HH && xm >= 0 && xm < WW) ? (ym * WW + xm) : -1;
    s_off[tid] = off;
    __syncthreads();

    const float* xb = x + (size_t)b * CIN * HWSZ;

    unsigned long long acc[32];
    #pragma unroll
    for (int op = 0; op < 32; op++) acc[op] = 0ull;

    const int wb_t = t * K2_TSTRIDE;

    for (int cb = 0; cb < 8; cb++) {
        // gather x at the masked position for 8 channels (coalesced across lanes)
        const int myoff = off;
        #pragma unroll
        for (int k = 0; k < 8; k++) {
            float v = (myoff >= 0) ? __ldg(xb + (cb * 8 + k) * HWSZ + myoff) : 0.0f;
            s_x[k * 256 + tid] = v;
        }
        // stage weight block [8c][9t][64o] with padded t-stride
        #pragma unroll
        for (int j = 0; j < 18; j++) {
            int f  = j * 256 + tid;            // 0..4607
            int o  = f / 72;
            int r  = f - 72 * o;
            int cl = r / 9;
            int tt = r - 9 * cl;
            s_w[cl * K2_CSTRIDE + tt * K2_TSTRIDE + o] =
                __ldg(w + o * (CIN * 9) + (cb * 8 + cl) * 9 + tt);
        }
        __syncthreads();

        #pragma unroll
        for (int cl = 0; cl < 8; cl++) {
            float xv = s_x[cl * 256 + tid];
            unsigned long long xd = pk2(xv, xv);
            const float* wp = &s_w[cl * K2_CSTRIDE + wb_t];
            #pragma unroll
            for (int op = 0; op < 32; op++) {
                unsigned long long w2 =
                    *reinterpret_cast<const unsigned long long*>(wp + 2 * op);
                ffma2(acc[op], xd, w2);
            }
        }
        __syncthreads();
    }

    // subtract (coalesced across lanes: consecutive l per fixed o)
    float* ob = out + (size_t)b * COUT * LTOT + l;
    #pragma unroll
    for (int op = 0; op < 32; op++) {
        float c0, c1;
        upk2(acc[op], c0, c1);
        ob[(2 * op + 0) * (size_t)LTOT] -= c0;
        ob[(2 * op + 1) * (size_t)LTOT] -= c1;
    }
}

// ================= launch =================
extern "C" void kernel_launch(void* const* d_in, const int* in_sizes, int n_in,
                              void* d_out, int out_size)
{
    (void)in_sizes; (void)n_in; (void)out_size;
    const float* x    = (const float*)d_in[0];
    const float* w    = (const float*)d_in[1];
    const int*   mask = (const int*)d_in[2];
    float*       out  = (float*)d_out;

    dim3 g1(WW / TW, HH / TH, BATCH);     // 7 x 14 x 8 = 784 CTAs
    conv_kernel<<<g1, NT1>>>(x, w, out);

    dim3 g2(LTOT / 256, BATCH);           // 49 x 8 = 392 CTAs
    corr_kernel<<<g2, 256>>>(x, w, mask, out);
}